// round 15
// baseline (speedup 1.0000x reference)
#include <cuda_runtime.h>
#include <cuda_bf16.h>
#include <cuda_fp16.h>
#include <stdint.h>
#include <math.h>

// B=8, M=1024, H=512, K=8 heads, D=64, SPAN=1024, MK=2048
#define DINLINE __device__ __forceinline__

// ---------------- scratch ----------------------------------------------------
__device__ __align__(16) __half g_Qh[64 * 1024 * 64];
__device__ __align__(16) __half g_Kh[64 * 2048 * 64];
__device__ __align__(16) __half g_Vh[64 * 2048 * 64];
__device__ __align__(16) __half g_Vth[64 * 64 * 2048];   // V^T [n][d][t]
__device__ __align__(16) __half g_Et[1024 * 64];         // E^T [s][d]
__device__ __align__(16) __half g_Xq16[8 * 1024 * 512];
__device__ __align__(16) __half g_Xk16[8 * 2048 * 512];
__device__ __align__(16) __half g_Xv16[8 * 2048 * 512];
__device__ __align__(16) __half g_WqT16[512 * 512];
__device__ __align__(16) __half g_WkT16[512 * 512];
__device__ __align__(16) __half g_WvT16[512 * 512];
__device__ __align__(16) __half g_WoT16[512 * 512];
__device__ __align__(16) __half g_Ch[8 * 1024 * 512], g_Cl[8 * 1024 * 512];

// ---------------- helpers ----------------------------------------------------
DINLINE void mma_f16(float c[4], uint32_t a0, uint32_t a1, uint32_t a2,
                     uint32_t a3, uint32_t b0, uint32_t b1) {
    asm volatile(
        "mma.sync.aligned.m16n8k16.row.col.f32.f16.f16.f32 "
        "{%0,%1,%2,%3}, {%4,%5,%6,%7}, {%8,%9}, {%0,%1,%2,%3};\n"
        : "+f"(c[0]), "+f"(c[1]), "+f"(c[2]), "+f"(c[3])
        : "r"(a0), "r"(a1), "r"(a2), "r"(a3), "r"(b0), "r"(b1));
}

DINLINE uint32_t smem_u32(const void* p) {
    return (uint32_t)__cvta_generic_to_shared(p);
}

DINLINE void cp16(uint32_t dst, const void* src) {
    asm volatile("cp.async.cg.shared.global [%0], [%1], 16;\n" ::"r"(dst),
                 "l"(src));
}
DINLINE void cp_commit() { asm volatile("cp.async.commit_group;\n" ::); }
template <int N>
DINLINE void cp_wait() {
    asm volatile("cp.async.wait_group %0;\n" ::"n"(N));
}

DINLINE void split_h(float x, __half& h, __half& l) {
    h = __float2half_rn(x);
    l = __float2half_rn(x - __half2float(h));
}

DINLINE void st_h2(__half* p, __half a, __half b) {
    __half2 t;
    t.x = a;
    t.y = b;
    *(__half2*)p = t;
}

DINLINE uint32_t pack_h2(float a, float b) {
    __half2 t = __floats2half2_rn(a, b);
    return *(uint32_t*)&t;
}

// ---------------- prep kernels --------------------------------------------------
__global__ void __launch_bounds__(256) conv_x(const float* __restrict__ in,
                                              __half* __restrict__ out, int n4) {
    int i = blockIdx.x * blockDim.x + threadIdx.x;
    if (i >= n4) return;
    float4 v = ((const float4*)in)[i];
    ((__half2*)out)[i * 2] = __floats2half2_rn(v.x, v.y);
    ((__half2*)out)[i * 2 + 1] = __floats2half2_rn(v.z, v.w);
}

// W[k][n] fp32 -> T[n][k] fp16
__global__ void __launch_bounds__(256) conv_wT_h(const float* __restrict__ W,
                                                 __half* __restrict__ Th) {
    __shared__ float tile[32][33];
    int tx = threadIdx.x & 31, ty = threadIdx.x >> 5;
    int n0 = blockIdx.x * 32, k0 = blockIdx.y * 32;
#pragma unroll
    for (int i = 0; i < 4; i++)
        tile[ty + i * 8][tx] = W[(size_t)(k0 + ty + i * 8) * 512 + n0 + tx];
    __syncthreads();
#pragma unroll
    for (int i = 0; i < 4; i++)
        Th[(size_t)(n0 + ty + i * 8) * 512 + k0 + tx] =
            __float2half_rn(tile[tx][ty + i * 8]);
}

// 16-bit [n][t][d] -> [n][d][t]
__global__ void __launch_bounds__(256) transpose_v(
    const uint16_t* __restrict__ in, uint16_t* __restrict__ out) {
    __shared__ uint16_t tile[32][33];
    int tx = threadIdx.x & 31, ty = threadIdx.x >> 5;
    int n = blockIdx.z;
    int t0 = blockIdx.x * 32, d0 = blockIdx.y * 32;
    const uint16_t* src = in + ((size_t)n * 2048 + t0) * 64 + d0;
#pragma unroll
    for (int i = 0; i < 4; i++)
        tile[ty + i * 8][tx] = src[(size_t)(ty + i * 8) * 64 + tx];
    __syncthreads();
    uint16_t* dst = out + ((size_t)n * 64 + d0) * 2048 + t0;
#pragma unroll
    for (int i = 0; i < 4; i++)
        dst[(size_t)(ty + i * 8) * 2048 + tx] = tile[tx][ty + i * 8];
}

// E fp32 [d][s] -> E^T fp16 [s][d]
__global__ void __launch_bounds__(256) conv_eT(const float* __restrict__ E,
                                               __half* __restrict__ Et) {
    __shared__ float tile[32][33];
    int tx = threadIdx.x & 31, ty = threadIdx.x >> 5;
    int s0 = blockIdx.x * 32, d0 = blockIdx.y * 32;
#pragma unroll
    for (int i = 0; i < 4; i++)
        tile[ty + i * 8][tx] = E[(size_t)(d0 + ty + i * 8) * 1024 + s0 + tx];
    __syncthreads();
#pragma unroll
    for (int i = 0; i < 4; i++)
        Et[(size_t)(s0 + ty + i * 8) * 64 + d0 + tx] =
            __float2half_rn(tile[tx][ty + i * 8]);
}

// ---------------- single-pass fp16 GEMM (Q/K/V projections) -------------------
constexpr int AS2 = 40;
constexpr int TSZ = 128 * AS2;

__global__ void __launch_bounds__(256, 1) gemm_h16(
    const __half* __restrict__ A_g, const __half* __restrict__ T_g,
    __half* __restrict__ outH, int T) {
    extern __shared__ __half smh[];

    const int tid = threadIdx.x;
    const int lane = tid & 31, wid = tid >> 5;
    const int wm = wid >> 2, wn = wid & 3;
    const int row0 = blockIdx.x * 128, col0 = blockIdx.y * 128;
    const int g = lane >> 2, t2 = (lane & 3) * 2;
    const int lr = tid >> 2;
    const int lc = (tid & 3) * 8;

    float acc[4][4][4] = {};

    {
        __half* As = smh;
        __half* Bs = As + TSZ;
#pragma unroll
        for (int half = 0; half < 2; half++) {
            int r = lr + half * 64;
            cp16(smem_u32(As + r * AS2 + lc), A_g + (size_t)(row0 + r) * 512 + lc);
            cp16(smem_u32(Bs + r * AS2 + lc), T_g + (size_t)(col0 + r) * 512 + lc);
        }
        cp_commit();
    }

    int buf = 0;
    for (int kk = 0; kk < 512; kk += 32) {
        if (kk + 32 < 512) {
            __half* As = smh + (buf ^ 1) * 2 * TSZ;
            __half* Bs = As + TSZ;
            int kn = kk + 32;
#pragma unroll
            for (int half = 0; half < 2; half++) {
                int r = lr + half * 64;
                cp16(smem_u32(As + r * AS2 + lc),
                     A_g + (size_t)(row0 + r) * 512 + kn + lc);
                cp16(smem_u32(Bs + r * AS2 + lc),
                     T_g + (size_t)(col0 + r) * 512 + kn + lc);
            }
            cp_commit();
            cp_wait<1>();
        } else {
            cp_wait<0>();
        }
        __syncthreads();

        const __half* As = smh + buf * 2 * TSZ;
        const __half* Bs = As + TSZ;
#pragma unroll
        for (int ks = 0; ks < 32; ks += 16) {
            uint32_t a[4][4], b[4][2];
#pragma unroll
            for (int mf = 0; mf < 4; mf++) {
                int rb = wm * 64 + mf * 16 + g;
                a[mf][0] = *(uint32_t*)&As[rb * AS2 + ks + t2];
                a[mf][1] = *(uint32_t*)&As[(rb + 8) * AS2 + ks + t2];
                a[mf][2] = *(uint32_t*)&As[rb * AS2 + ks + 8 + t2];
                a[mf][3] = *(uint32_t*)&As[(rb + 8) * AS2 + ks + 8 + t2];
            }
#pragma unroll
            for (int nf = 0; nf < 4; nf++) {
                int cb = wn * 32 + nf * 8 + g;
                b[nf][0] = *(uint32_t*)&Bs[cb * AS2 + ks + t2];
                b[nf][1] = *(uint32_t*)&Bs[cb * AS2 + ks + 8 + t2];
            }
#pragma unroll
            for (int mf = 0; mf < 4; mf++)
#pragma unroll
                for (int nf = 0; nf < 4; nf++)
                    mma_f16(acc[mf][nf], a[mf][0], a[mf][1], a[mf][2],
                            a[mf][3], b[nf][0], b[nf][1]);
        }
        __syncthreads();
        buf ^= 1;
    }

#pragma unroll
    for (int mf = 0; mf < 4; mf++) {
#pragma unroll
        for (int nf = 0; nf < 4; nf++) {
            int rr = row0 + wm * 64 + mf * 16 + g;
            int cc = col0 + wn * 32 + nf * 8 + t2;
            int head = cc >> 6, d = cc & 63;
#pragma unroll
            for (int rh = 0; rh < 2; rh++) {
                int grow = rr + rh * 8;
                int b = grow / T, t = grow - b * T;
                size_t idx = (((size_t)(b * 8 + head) * T + t) << 6) + d;
                st_h2(outH + idx, __float2half_rn(acc[mf][nf][rh * 2 + 0]),
                      __float2half_rn(acc[mf][nf][rh * 2 + 1]));
            }
        }
    }
}

// ---------------- 2-pass fp16 GEMM for output projection -----------------------
// out = (Ch + Cl) @ Wo  with Ch/Cl fp16, Wo^T fp16.
__global__ void __launch_bounds__(256, 1) gemm_out2(
    const __half* __restrict__ Ah_g, const __half* __restrict__ Al_g,
    const __half* __restrict__ T_g, float* __restrict__ outF) {
    extern __shared__ __half smh[];

    const int tid = threadIdx.x;
    const int lane = tid & 31, wid = tid >> 5;
    const int wm = wid >> 2, wn = wid & 3;
    const int row0 = blockIdx.x * 128, col0 = blockIdx.y * 128;
    const int g = lane >> 2, t2 = (lane & 3) * 2;
    const int lr = tid >> 2;
    const int lc = (tid & 3) * 8;

    float acc[4][4][4] = {};

    {
        __half* Ah = smh;
        __half* Al = Ah + TSZ;
        __half* Bs = Al + TSZ;
#pragma unroll
        for (int half = 0; half < 2; half++) {
            int r = lr + half * 64;
            cp16(smem_u32(Ah + r * AS2 + lc), Ah_g + (size_t)(row0 + r) * 512 + lc);
            cp16(smem_u32(Al + r * AS2 + lc), Al_g + (size_t)(row0 + r) * 512 + lc);
            cp16(smem_u32(Bs + r * AS2 + lc), T_g + (size_t)(col0 + r) * 512 + lc);
        }
        cp_commit();
    }

    int buf = 0;
    for (int kk = 0; kk < 512; kk += 32) {
        if (kk + 32 < 512) {
            __half* Ah = smh + (buf ^ 1) * 3 * TSZ;
            __half* Al = Ah + TSZ;
            __half* Bs = Al + TSZ;
            int kn = kk + 32;
#pragma unroll
            for (int half = 0; half < 2; half++) {
                int r = lr + half * 64;
                cp16(smem_u32(Ah + r * AS2 + lc),
                     Ah_g + (size_t)(row0 + r) * 512 + kn + lc);
                cp16(smem_u32(Al + r * AS2 + lc),
                     Al_g + (size_t)(row0 + r) * 512 + kn + lc);
                cp16(smem_u32(Bs + r * AS2 + lc),
                     T_g + (size_t)(col0 + r) * 512 + kn + lc);
            }
            cp_commit();
            cp_wait<1>();
        } else {
            cp_wait<0>();
        }
        __syncthreads();

        const __half* Ah = smh + buf * 3 * TSZ;
        const __half* Al = Ah + TSZ;
        const __half* Bs = Al + TSZ;
#pragma unroll
        for (int ks = 0; ks < 32; ks += 16) {
            uint32_t ah[4][4], al[4][4], b[4][2];
#pragma unroll
            for (int mf = 0; mf < 4; mf++) {
                int rb = wm * 64 + mf * 16 + g;
                ah[mf][0] = *(uint32_t*)&Ah[rb * AS2 + ks + t2];
                ah[mf][1] = *(uint32_t*)&Ah[(rb + 8) * AS2 + ks + t2];
                ah[mf][2] = *(uint32_t*)&Ah[rb * AS2 + ks + 8 + t2];
                ah[mf][3] = *(uint32_t*)&Ah[(rb + 8) * AS2 + ks + 8 + t2];
                al[mf][0] = *(uint32_t*)&Al[rb * AS2 + ks + t2];
                al[mf][1] = *(uint32_t*)&Al[(rb + 8) * AS2 + ks + t2];
                al[mf][2] = *(uint32_t*)&Al[rb * AS2 + ks + 8 + t2];
                al[mf][3] = *(uint32_t*)&Al[(rb + 8) * AS2 + ks + 8 + t2];
            }
#pragma unroll
            for (int nf = 0; nf < 4; nf++) {
                int cb = wn * 32 + nf * 8 + g;
                b[nf][0] = *(uint32_t*)&Bs[cb * AS2 + ks + t2];
                b[nf][1] = *(uint32_t*)&Bs[cb * AS2 + ks + 8 + t2];
            }
#pragma unroll
            for (int mf = 0; mf < 4; mf++)
#pragma unroll
                for (int nf = 0; nf < 4; nf++) {
                    mma_f16(acc[mf][nf], ah[mf][0], ah[mf][1], ah[mf][2],
                            ah[mf][3], b[nf][0], b[nf][1]);
                    mma_f16(acc[mf][nf], al[mf][0], al[mf][1], al[mf][2],
                            al[mf][3], b[nf][0], b[nf][1]);
                }
        }
        __syncthreads();
        buf ^= 1;
    }

#pragma unroll
    for (int mf = 0; mf < 4; mf++) {
#pragma unroll
        for (int nf = 0; nf < 4; nf++) {
            int rr = row0 + wm * 64 + mf * 16 + g;
            int cc = col0 + wn * 32 + nf * 8 + t2;
            *(float2*)&outF[(size_t)rr * 512 + cc] =
                make_float2(acc[mf][nf][0], acc[mf][nf][1]);
            *(float2*)&outF[(size_t)(rr + 8) * 512 + cc] =
                make_float2(acc[mf][nf][2], acc[mf][nf][3]);
        }
    }
}

// ---------------- fused banded attention v12 -----------------------------------
// v11 + warp-uniform dead-tile skipping (exact) + fp16 QE staging + fp16 C out.
__global__ void __launch_bounds__(256, 1) attn_tc12(
    const __half* __restrict__ Qg, const __half* __restrict__ Kg,
    const __half* __restrict__ Vth, const __half* __restrict__ Et,
    __half* __restrict__ Ch, __half* __restrict__ Cl) {
    constexpr int QS = 72, KS = 72, ES = 72, VS = 200, QES = 132, OS = 68;
    extern __shared__ char smraw[];
    __half* Qsh = (__half*)smraw;                // [64][QS]
    __half* Ksh = Qsh + 64 * QS;                 // [192][KS]
    __half* Esh = Ksh + 192 * KS;                // [128][ES]
    __half* Vsh = Esh + 128 * ES;                // [64][VS]
    __half* QEs = Vsh + 64 * VS;                 // [64][QES] fp16
    float* mls = (float*)(QEs + 64 * QES);       // [4][64]
    float* lls = mls + 256;                      // [4][64]
    float* Ored = (float*)Ksh;                   // epilogue alias (needs 69632B;
                                                 // K+E+V = 71680B available)

    const int tid = threadIdx.x, lane = tid & 31, wid = tid >> 5;
    const int wm = wid >> 2, wn = wid & 3;  // 2 x 4 warps
    const int g = lane >> 2, t2 = (lane & 3) * 2;
    const int n = blockIdx.y, m0 = blockIdx.x * 64;
    const float SCl2 = 0.125f * 1.4426950408889634f;
    const int cb0 = wn * 48;

    // warp-uniform live predicates (band is position-invariant across chunks)
    bool liveQK[2][6], livePV[2][3];
#pragma unroll
    for (int mf = 0; mf < 2; mf++) {
        int R0 = wm * 32 + mf * 16;
#pragma unroll
        for (int nf = 0; nf < 6; nf++) {
            int c0 = cb0 + nf * 8;
            liveQK[mf][nf] = (c0 + 7 >= R0) && (c0 <= R0 + 142);
        }
#pragma unroll
        for (int k = 0; k < 3; k++) {
            int c0 = cb0 + k * 16;
            livePV[mf][k] = (c0 + 15 >= R0) && (c0 <= R0 + 142);
        }
    }

    auto issue_KE = [&](int c) {
        const size_t kbase = ((size_t)n * 2048 + m0 + c * 128) << 6;
        const __half* sh = Kg + kbase;
#pragma unroll
        for (int it = 0; it < 6; it++) {
            int f = tid + it * 256;
            int kr = f >> 3, j = (f & 7) * 8;
            cp16(smem_u32(Ksh + kr * KS + j), sh + f * 8);
        }
        const __half* es = Et + (size_t)(c * 128) * 64;
#pragma unroll
        for (int it = 0; it < 4; it++) {
            int f = tid + it * 256;
            int s = f >> 3, j = (f & 7) * 8;
            cp16(smem_u32(Esh + s * ES + j), es + f * 8);
        }
    };
    auto issue_V = [&](int c) {
        const __half* vh = Vth + (size_t)n * 64 * 2048 + m0 + c * 128;
#pragma unroll
        for (int it = 0; it < 6; it++) {
            int f = tid + it * 256;
            int d = f / 24, j = f - d * 24;
            cp16(smem_u32(Vsh + d * VS + j * 8), vh + (size_t)d * 2048 + j * 8);
        }
    };

    // stage Q tile
    {
        const uint4* sh = (const uint4*)(Qg + (((size_t)n * 1024 + m0) << 6));
#pragma unroll
        for (int it = 0; it < 2; it++) {
            int f = tid + it * 256;
            int m = f >> 3, j = f & 7;
            ((uint4*)(Qsh + m * QS))[j] = sh[f];
        }
    }

    issue_KE(0);
    cp_commit();
    issue_V(0);
    cp_commit();

    float o[2][8][4] = {};
    float mreg[2][2] = {{-1e30f, -1e30f}, {-1e30f, -1e30f}};
    float lreg[2][2] = {};

    for (int c = 0; c < 8; c++) {
        cp_wait<1>();
        __syncthreads();

        // ---- fused QK (1 pass, dead tiles skipped) + QE (1 pass) ----
        float sAcc[2][6][4] = {};
        float qeAcc[2][4][4] = {};
#pragma unroll
        for (int ks = 0; ks < 64; ks += 16) {
            uint32_t ah[2][4];
#pragma unroll
            for (int mf = 0; mf < 2; mf++) {
                int rb = wm * 32 + mf * 16 + g;
                ah[mf][0] = *(uint32_t*)&Qsh[rb * QS + ks + t2];
                ah[mf][1] = *(uint32_t*)&Qsh[(rb + 8) * QS + ks + t2];
                ah[mf][2] = *(uint32_t*)&Qsh[rb * QS + ks + 8 + t2];
                ah[mf][3] = *(uint32_t*)&Qsh[(rb + 8) * QS + ks + 8 + t2];
            }
#pragma unroll
            for (int nf = 0; nf < 6; nf++) {
                if (!liveQK[0][nf] && !liveQK[1][nf]) continue;
                int cb = cb0 + nf * 8 + g;
                uint32_t kb0 = *(uint32_t*)&Ksh[cb * KS + ks + t2];
                uint32_t kb1 = *(uint32_t*)&Ksh[cb * KS + ks + 8 + t2];
#pragma unroll
                for (int mf = 0; mf < 2; mf++)
                    if (liveQK[mf][nf])
                        mma_f16(sAcc[mf][nf], ah[mf][0], ah[mf][1], ah[mf][2],
                                ah[mf][3], kb0, kb1);
            }
#pragma unroll
            for (int nf = 0; nf < 4; nf++) {
                int cb = wn * 32 + nf * 8 + g;
                uint32_t eb0 = *(uint32_t*)&Esh[cb * ES + ks + t2];
                uint32_t eb1 = *(uint32_t*)&Esh[cb * ES + ks + 8 + t2];
#pragma unroll
                for (int mf = 0; mf < 2; mf++)
                    mma_f16(qeAcc[mf][nf], ah[mf][0], ah[mf][1], ah[mf][2],
                            ah[mf][3], eb0, eb1);
            }
        }
        // stage QE fragments (fp16)
#pragma unroll
        for (int mf = 0; mf < 2; mf++) {
            int R = wm * 32 + mf * 16 + g;
#pragma unroll
            for (int nf = 0; nf < 4; nf++) {
                int cc = wn * 32 + nf * 8 + t2;
                *(uint32_t*)&QEs[R * QES + cc] =
                    pack_h2(qeAcc[mf][nf][0], qeAcc[mf][nf][1]);
                *(uint32_t*)&QEs[(R + 8) * QES + cc] =
                    pack_h2(qeAcc[mf][nf][2], qeAcc[mf][nf][3]);
            }
        }
        __syncthreads();

        if (c < 7) issue_KE(c + 1);
        cp_commit();

        // ---- warp-local masked softmax (dead tiles skipped) ----
        uint32_t pf[2][3][4];
#pragma unroll
        for (int mf = 0; mf < 2; mf++) {
            int R = wm * 32 + mf * 16 + g;
            float mx0 = -3e38f, mx1 = -3e38f;
#pragma unroll
            for (int nf = 0; nf < 6; nf++) {
                if (!liveQK[mf][nf]) continue;
                int cc = cb0 + nf * 8 + t2;
#pragma unroll
                for (int e = 0; e < 4; e++) {
                    int r = R + ((e >> 1) << 3);
                    int col = cc + (e & 1);
                    int diff = col - r;
                    float z = -3e38f;
                    if ((unsigned)diff < 128u)
                        z = sAcc[mf][nf][e] +
                            __half2float(QEs[r * QES + diff]);
                    sAcc[mf][nf][e] = z;
                    if (e < 2) mx0 = fmaxf(mx0, z);
                    else mx1 = fmaxf(mx1, z);
                }
            }
            mx0 = fmaxf(mx0, __shfl_xor_sync(0xffffffffu, mx0, 1));
            mx0 = fmaxf(mx0, __shfl_xor_sync(0xffffffffu, mx0, 2));
            mx1 = fmaxf(mx1, __shfl_xor_sync(0xffffffffu, mx1, 1));
            mx1 = fmaxf(mx1, __shfl_xor_sync(0xffffffffu, mx1, 2));
            float mn0 = fmaxf(mreg[mf][0], mx0 * SCl2);
            float mn1 = fmaxf(mreg[mf][1], mx1 * SCl2);
            float al0 = exp2f(mreg[mf][0] - mn0);
            float al1 = exp2f(mreg[mf][1] - mn1);
            float sum0 = 0.f, sum1 = 0.f;
#pragma unroll
            for (int nf = 0; nf < 6; nf++) {
                int k = nf >> 1, hf = (nf & 1) * 2;
                if (!liveQK[mf][nf]) {
                    pf[mf][k][hf + 0] = 0u;
                    pf[mf][k][hf + 1] = 0u;
                    continue;
                }
                float p0 = exp2f(sAcc[mf][nf][0] * SCl2 - mn0);
                float p1 = exp2f(sAcc[mf][nf][1] * SCl2 - mn0);
                float p2 = exp2f(sAcc[mf][nf][2] * SCl2 - mn1);
                float p3 = exp2f(sAcc[mf][nf][3] * SCl2 - mn1);
                sum0 += p0 + p1;
                sum1 += p2 + p3;
                pf[mf][k][hf + 0] = pack_h2(p0, p1);
                pf[mf][k][hf + 1] = pack_h2(p2, p3);
            }
            sum0 += __shfl_xor_sync(0xffffffffu, sum0, 1);
            sum0 += __shfl_xor_sync(0xffffffffu, sum0, 2);
            sum1 += __shfl_xor_sync(0xffffffffu, sum1, 1);
            sum1 += __shfl_xor_sync(0xffffffffu, sum1, 2);
            lreg[mf][0] = lreg[mf][0] * al0 + sum0;
            lreg[mf][1] = lreg[mf][1] * al1 + sum1;
            mreg[mf][0] = mn0;
            mreg[mf][1] = mn1;
#pragma unroll
            for (int nfd = 0; nfd < 8; nfd++) {
                o[mf][nfd][0] *= al0;
                o[mf][nfd][1] *= al0;
                o[mf][nfd][2] *= al1;
                o[mf][nfd][3] *= al1;
            }
        }
        cp_wait<1>();
        __syncthreads();

        // ---- PV: 1 pass fp16, dead P-tiles skipped ----
#pragma unroll
        for (int k = 0; k < 3; k++) {
            if (!livePV[0][k] && !livePV[1][k]) continue;
            int ks = cb0 + k * 16;
#pragma unroll
            for (int nfd = 0; nfd < 8; nfd++) {
                int cb = nfd * 8 + g;
                uint32_t vh0 = *(uint32_t*)&Vsh[cb * VS + ks + t2];
                uint32_t vh1 = *(uint32_t*)&Vsh[cb * VS + ks + 8 + t2];
#pragma unroll
                for (int mf = 0; mf < 2; mf++)
                    if (livePV[mf][k])
                        mma_f16(o[mf][nfd], pf[mf][k][0], pf[mf][k][1],
                                pf[mf][k][2], pf[mf][k][3], vh0, vh1);
            }
        }
        __syncthreads();

        if (c < 7) issue_V(c + 1);
        cp_commit();
    }

    // ---- epilogue: cross-warp merge + normalize + store (fp16 hi/lo) ----
    {
        int wbase = (wm * 4 + wn) * 32;
#pragma unroll
        for (int mf = 0; mf < 2; mf++) {
            int lr0 = mf * 16 + g;
            if ((lane & 3) == 0) {
                mls[wn * 64 + wm * 32 + lr0] = mreg[mf][0];
                mls[wn * 64 + wm * 32 + lr0 + 8] = mreg[mf][1];
                lls[wn * 64 + wm * 32 + lr0] = lreg[mf][0];
                lls[wn * 64 + wm * 32 + lr0 + 8] = lreg[mf][1];
            }
#pragma unroll
            for (int nfd = 0; nfd < 8; nfd++) {
                int cc = nfd * 8 + t2;
                *(float2*)&Ored[(wbase + lr0) * OS + cc] =
                    make_float2(o[mf][nfd][0], o[mf][nfd][1]);
                *(float2*)&Ored[(wbase + lr0 + 8) * OS + cc] =
                    make_float2(o[mf][nfd][2], o[mf][nfd][3]);
            }
        }
    }
    __syncthreads();
    {
        const int b = n >> 3, kh = n & 7;
#pragma unroll
        for (int u = 0; u < 4; u++) {
            int id = tid + u * 256;
            int r = id >> 4;
            int c4 = (id & 15) * 4;
            int wmr = r >> 5, lr = r & 31;
            float mw0 = mls[r], mw1 = mls[64 + r], mw2 = mls[128 + r],
                  mw3 = mls[192 + r];
            float ms = fmaxf(fmaxf(mw0, mw1), fmaxf(mw2, mw3));
            float e0 = exp2f(mw0 - ms), e1 = exp2f(mw1 - ms),
                  e2 = exp2f(mw2 - ms), e3 = exp2f(mw3 - ms);
            float lt = lls[r] * e0 + lls[64 + r] * e1 + lls[128 + r] * e2 +
                       lls[192 + r] * e3;
            float4 s0 = *(float4*)&Ored[((wmr * 4 + 0) * 32 + lr) * OS + c4];
            float4 s1 = *(float4*)&Ored[((wmr * 4 + 1) * 32 + lr) * OS + c4];
            float4 s2 = *(float4*)&Ored[((wmr * 4 + 2) * 32 + lr) * OS + c4];
            float4 s3 = *(float4*)&Ored[((wmr * 4 + 3) * 32 + lr) * OS + c4];
            float inv = 1.0f / lt;
            float x = (s0.x * e0 + s1.x * e1 + s2.x * e2 + s3.x * e3) * inv;
            float y = (s0.y * e0 + s1.y * e1 + s2.y * e2 + s3.y * e3) * inv;
            float z = (s0.z * e0 + s1.z * e1 + s2.z * e2 + s3.z * e3) * inv;
            float w = (s0.w * e0 + s1.w * e1 + s2.w * e2 + s3.w * e3) * inv;
            __half h0, l0, h1, l1, h2, l2, h3, l3;
            split_h(x, h0, l0);
            split_h(y, h1, l1);
            split_h(z, h2, l2);
            split_h(w, h3, l3);
            size_t base = ((size_t)b * 1024 + m0 + r) * 512 + kh * 64 + c4;
            st_h2(&Ch[base], h0, h1);
            st_h2(&Ch[base + 2], h2, h3);
            st_h2(&Cl[base], l0, l1);
            st_h2(&Cl[base + 2], l2, l3);
        }
    }
}

// ---------------- launcher ----------------------------------------------------
extern "C" void kernel_launch(void* const* d_in, const int* in_sizes, int n_in,
                              void* d_out, int out_size) {
    const float* query = (const float*)d_in[0];
    const float* key = (const float*)d_in[1];
    const float* value = (const float*)d_in[2];
    const float* pos = (const float*)d_in[3];
    const float* Wq = (const float*)d_in[4];
    const float* Wk = (const float*)d_in[5];
    const float* Wv = (const float*)d_in[6];
    const float* Wo = (const float*)d_in[7];
    float* out = (float*)d_out;

    __half *qg, *kg, *vh, *vth, *et;
    __half *xq, *xk, *xv, *wqt, *wkt, *wvt, *wot, *ch, *cl;
    cudaGetSymbolAddress((void**)&qg, g_Qh);
    cudaGetSymbolAddress((void**)&kg, g_Kh);
    cudaGetSymbolAddress((void**)&vh, g_Vh);
    cudaGetSymbolAddress((void**)&vth, g_Vth);
    cudaGetSymbolAddress((void**)&et, g_Et);
    cudaGetSymbolAddress((void**)&xq, g_Xq16);
    cudaGetSymbolAddress((void**)&xk, g_Xk16);
    cudaGetSymbolAddress((void**)&xv, g_Xv16);
    cudaGetSymbolAddress((void**)&wqt, g_WqT16);
    cudaGetSymbolAddress((void**)&wkt, g_WkT16);
    cudaGetSymbolAddress((void**)&wvt, g_WvT16);
    cudaGetSymbolAddress((void**)&wot, g_WoT16);
    cudaGetSymbolAddress((void**)&ch, g_Ch);
    cudaGetSymbolAddress((void**)&cl, g_Cl);

    // prep
    conv_x<<<4096, 256>>>(query, xq, 1048576);
    conv_x<<<8192, 256>>>(key, xk, 2097152);
    conv_x<<<8192, 256>>>(value, xv, 2097152);
    conv_wT_h<<<dim3(16, 16), 256>>>(Wq, wqt);
    conv_wT_h<<<dim3(16, 16), 256>>>(Wk, wkt);
    conv_wT_h<<<dim3(16, 16), 256>>>(Wv, wvt);
    conv_wT_h<<<dim3(16, 16), 256>>>(Wo, wot);
    conv_eT<<<dim3(32, 2), 256>>>(pos, et);

    // projections (single-pass fp16)
    const int hsm = 2 * 2 * TSZ * 2;  // 40960 bytes
    cudaFuncSetAttribute(gemm_h16, cudaFuncAttributeMaxDynamicSharedMemorySize,
                         hsm);
    gemm_h16<<<dim3(64, 4), 256, hsm>>>(xq, wqt, qg, 1024);
    gemm_h16<<<dim3(128, 4), 256, hsm>>>(xk, wkt, kg, 2048);
    gemm_h16<<<dim3(128, 4), 256, hsm>>>(xv, wvt, vh, 2048);

    // V transpose to [n][d][t]
    transpose_v<<<dim3(64, 2, 64), 256>>>((const uint16_t*)vh, (uint16_t*)vth);

    // attention
    const int smem_bytes =
        (64 * 72 + 192 * 72 + 128 * 72 + 64 * 200 + 64 * 132) * 2 +
        (256 + 256) * 4;  // 101888
    cudaFuncSetAttribute(attn_tc12, cudaFuncAttributeMaxDynamicSharedMemorySize,
                         smem_bytes);
    attn_tc12<<<dim3(16, 64), 256, smem_bytes>>>(qg, kg, vth, et, ch, cl);

    // output projection (2-pass fp16)
    const int osm = 2 * 3 * TSZ * 2;  // 61440 bytes
    cudaFuncSetAttribute(gemm_out2, cudaFuncAttributeMaxDynamicSharedMemorySize,
                         osm);
    gemm_out2<<<dim3(64, 4), 256, osm>>>(ch, cl, wot, out);
}

// round 16
// speedup vs baseline: 1.1922x; 1.1922x over previous
#include <cuda_runtime.h>
#include <cuda_bf16.h>
#include <cuda_fp16.h>
#include <stdint.h>
#include <math.h>

// B=8, M=1024, H=512, K=8 heads, D=64, SPAN=1024, MK=2048
#define DINLINE __device__ __forceinline__

// ---------------- scratch ----------------------------------------------------
__device__ __align__(16) __half g_Qh[64 * 1024 * 64];
__device__ __align__(16) __half g_Kh[64 * 2048 * 64];
__device__ __align__(16) __half g_Vh[64 * 2048 * 64];
__device__ __align__(16) __half g_Vth[64 * 64 * 2048];   // V^T [n][d][t]
__device__ __align__(16) __half g_Et[1024 * 64];         // E^T [s][d]
__device__ __align__(16) __half g_Xq16[8 * 1024 * 512];
__device__ __align__(16) __half g_Xk16[8 * 2048 * 512];
__device__ __align__(16) __half g_Xv16[8 * 2048 * 512];
__device__ __align__(16) __half g_WqT16[512 * 512];
__device__ __align__(16) __half g_WkT16[512 * 512];
__device__ __align__(16) __half g_WvT16[512 * 512];
__device__ __align__(16) __half g_WoT16[512 * 512];
__device__ __align__(16) __half g_Ch[8 * 1024 * 512], g_Cl[8 * 1024 * 512];

// ---------------- helpers ----------------------------------------------------
DINLINE void mma_f16(float c[4], uint32_t a0, uint32_t a1, uint32_t a2,
                     uint32_t a3, uint32_t b0, uint32_t b1) {
    asm volatile(
        "mma.sync.aligned.m16n8k16.row.col.f32.f16.f16.f32 "
        "{%0,%1,%2,%3}, {%4,%5,%6,%7}, {%8,%9}, {%0,%1,%2,%3};\n"
        : "+f"(c[0]), "+f"(c[1]), "+f"(c[2]), "+f"(c[3])
        : "r"(a0), "r"(a1), "r"(a2), "r"(a3), "r"(b0), "r"(b1));
}

DINLINE uint32_t smem_u32(const void* p) {
    return (uint32_t)__cvta_generic_to_shared(p);
}

DINLINE void cp16(uint32_t dst, const void* src) {
    asm volatile("cp.async.cg.shared.global [%0], [%1], 16;\n" ::"r"(dst),
                 "l"(src));
}
DINLINE void cp_commit() { asm volatile("cp.async.commit_group;\n" ::); }
template <int N>
DINLINE void cp_wait() {
    asm volatile("cp.async.wait_group %0;\n" ::"n"(N));
}

DINLINE void split_h(float x, __half& h, __half& l) {
    h = __float2half_rn(x);
    l = __float2half_rn(x - __half2float(h));
}

DINLINE void st_h2(__half* p, __half a, __half b) {
    __half2 t;
    t.x = a;
    t.y = b;
    *(__half2*)p = t;
}

DINLINE uint32_t pack_h2(float a, float b) {
    __half2 t = __floats2half2_rn(a, b);
    return *(uint32_t*)&t;
}

// ---------------- prep kernels --------------------------------------------------
__global__ void __launch_bounds__(256) conv_x(const float* __restrict__ in,
                                              __half* __restrict__ out, int n4) {
    int i = blockIdx.x * blockDim.x + threadIdx.x;
    if (i >= n4) return;
    float4 v = ((const float4*)in)[i];
    ((__half2*)out)[i * 2] = __floats2half2_rn(v.x, v.y);
    ((__half2*)out)[i * 2 + 1] = __floats2half2_rn(v.z, v.w);
}

// W[k][n] fp32 -> T[n][k] fp16
__global__ void __launch_bounds__(256) conv_wT_h(const float* __restrict__ W,
                                                 __half* __restrict__ Th) {
    __shared__ float tile[32][33];
    int tx = threadIdx.x & 31, ty = threadIdx.x >> 5;
    int n0 = blockIdx.x * 32, k0 = blockIdx.y * 32;
#pragma unroll
    for (int i = 0; i < 4; i++)
        tile[ty + i * 8][tx] = W[(size_t)(k0 + ty + i * 8) * 512 + n0 + tx];
    __syncthreads();
#pragma unroll
    for (int i = 0; i < 4; i++)
        Th[(size_t)(n0 + ty + i * 8) * 512 + k0 + tx] =
            __float2half_rn(tile[tx][ty + i * 8]);
}

// 16-bit [n][t][d] -> [n][d][t]
__global__ void __launch_bounds__(256) transpose_v(
    const uint16_t* __restrict__ in, uint16_t* __restrict__ out) {
    __shared__ uint16_t tile[32][33];
    int tx = threadIdx.x & 31, ty = threadIdx.x >> 5;
    int n = blockIdx.z;
    int t0 = blockIdx.x * 32, d0 = blockIdx.y * 32;
    const uint16_t* src = in + ((size_t)n * 2048 + t0) * 64 + d0;
#pragma unroll
    for (int i = 0; i < 4; i++)
        tile[ty + i * 8][tx] = src[(size_t)(ty + i * 8) * 64 + tx];
    __syncthreads();
    uint16_t* dst = out + ((size_t)n * 64 + d0) * 2048 + t0;
#pragma unroll
    for (int i = 0; i < 4; i++)
        dst[(size_t)(ty + i * 8) * 2048 + tx] = tile[tx][ty + i * 8];
}

// E fp32 [d][s] -> E^T fp16 [s][d]
__global__ void __launch_bounds__(256) conv_eT(const float* __restrict__ E,
                                               __half* __restrict__ Et) {
    __shared__ float tile[32][33];
    int tx = threadIdx.x & 31, ty = threadIdx.x >> 5;
    int s0 = blockIdx.x * 32, d0 = blockIdx.y * 32;
#pragma unroll
    for (int i = 0; i < 4; i++)
        tile[ty + i * 8][tx] = E[(size_t)(d0 + ty + i * 8) * 1024 + s0 + tx];
    __syncthreads();
#pragma unroll
    for (int i = 0; i < 4; i++)
        Et[(size_t)(s0 + ty + i * 8) * 64 + d0 + tx] =
            __float2half_rn(tile[tx][ty + i * 8]);
}

// ---------------- single-pass fp16 GEMM (Q/K/V projections) -------------------
constexpr int AS2 = 40;
constexpr int TSZ = 128 * AS2;

__global__ void __launch_bounds__(256, 1) gemm_h16(
    const __half* __restrict__ A_g, const __half* __restrict__ T_g,
    __half* __restrict__ outH, int T) {
    extern __shared__ __half smh[];

    const int tid = threadIdx.x;
    const int lane = tid & 31, wid = tid >> 5;
    const int wm = wid >> 2, wn = wid & 3;
    const int row0 = blockIdx.x * 128, col0 = blockIdx.y * 128;
    const int g = lane >> 2, t2 = (lane & 3) * 2;
    const int lr = tid >> 2;
    const int lc = (tid & 3) * 8;

    float acc[4][4][4] = {};

    {
        __half* As = smh;
        __half* Bs = As + TSZ;
#pragma unroll
        for (int half = 0; half < 2; half++) {
            int r = lr + half * 64;
            cp16(smem_u32(As + r * AS2 + lc), A_g + (size_t)(row0 + r) * 512 + lc);
            cp16(smem_u32(Bs + r * AS2 + lc), T_g + (size_t)(col0 + r) * 512 + lc);
        }
        cp_commit();
    }

    int buf = 0;
    for (int kk = 0; kk < 512; kk += 32) {
        if (kk + 32 < 512) {
            __half* As = smh + (buf ^ 1) * 2 * TSZ;
            __half* Bs = As + TSZ;
            int kn = kk + 32;
#pragma unroll
            for (int half = 0; half < 2; half++) {
                int r = lr + half * 64;
                cp16(smem_u32(As + r * AS2 + lc),
                     A_g + (size_t)(row0 + r) * 512 + kn + lc);
                cp16(smem_u32(Bs + r * AS2 + lc),
                     T_g + (size_t)(col0 + r) * 512 + kn + lc);
            }
            cp_commit();
            cp_wait<1>();
        } else {
            cp_wait<0>();
        }
        __syncthreads();

        const __half* As = smh + buf * 2 * TSZ;
        const __half* Bs = As + TSZ;
#pragma unroll
        for (int ks = 0; ks < 32; ks += 16) {
            uint32_t a[4][4], b[4][2];
#pragma unroll
            for (int mf = 0; mf < 4; mf++) {
                int rb = wm * 64 + mf * 16 + g;
                a[mf][0] = *(uint32_t*)&As[rb * AS2 + ks + t2];
                a[mf][1] = *(uint32_t*)&As[(rb + 8) * AS2 + ks + t2];
                a[mf][2] = *(uint32_t*)&As[rb * AS2 + ks + 8 + t2];
                a[mf][3] = *(uint32_t*)&As[(rb + 8) * AS2 + ks + 8 + t2];
            }
#pragma unroll
            for (int nf = 0; nf < 4; nf++) {
                int cb = wn * 32 + nf * 8 + g;
                b[nf][0] = *(uint32_t*)&Bs[cb * AS2 + ks + t2];
                b[nf][1] = *(uint32_t*)&Bs[cb * AS2 + ks + 8 + t2];
            }
#pragma unroll
            for (int mf = 0; mf < 4; mf++)
#pragma unroll
                for (int nf = 0; nf < 4; nf++)
                    mma_f16(acc[mf][nf], a[mf][0], a[mf][1], a[mf][2],
                            a[mf][3], b[nf][0], b[nf][1]);
        }
        __syncthreads();
        buf ^= 1;
    }

#pragma unroll
    for (int mf = 0; mf < 4; mf++) {
#pragma unroll
        for (int nf = 0; nf < 4; nf++) {
            int rr = row0 + wm * 64 + mf * 16 + g;
            int cc = col0 + wn * 32 + nf * 8 + t2;
            int head = cc >> 6, d = cc & 63;
#pragma unroll
            for (int rh = 0; rh < 2; rh++) {
                int grow = rr + rh * 8;
                int b = grow / T, t = grow - b * T;
                size_t idx = (((size_t)(b * 8 + head) * T + t) << 6) + d;
                st_h2(outH + idx, __float2half_rn(acc[mf][nf][rh * 2 + 0]),
                      __float2half_rn(acc[mf][nf][rh * 2 + 1]));
            }
        }
    }
}

// ---------------- 2-pass fp16 GEMM for output projection -----------------------
// out = (Ch + Cl) @ Wo  with Ch/Cl fp16, Wo^T fp16.
__global__ void __launch_bounds__(256, 1) gemm_out2(
    const __half* __restrict__ Ah_g, const __half* __restrict__ Al_g,
    const __half* __restrict__ T_g, float* __restrict__ outF) {
    extern __shared__ __half smh[];

    const int tid = threadIdx.x;
    const int lane = tid & 31, wid = tid >> 5;
    const int wm = wid >> 2, wn = wid & 3;
    const int row0 = blockIdx.x * 128, col0 = blockIdx.y * 128;
    const int g = lane >> 2, t2 = (lane & 3) * 2;
    const int lr = tid >> 2;
    const int lc = (tid & 3) * 8;

    float acc[4][4][4] = {};

    {
        __half* Ah = smh;
        __half* Al = Ah + TSZ;
        __half* Bs = Al + TSZ;
#pragma unroll
        for (int half = 0; half < 2; half++) {
            int r = lr + half * 64;
            cp16(smem_u32(Ah + r * AS2 + lc), Ah_g + (size_t)(row0 + r) * 512 + lc);
            cp16(smem_u32(Al + r * AS2 + lc), Al_g + (size_t)(row0 + r) * 512 + lc);
            cp16(smem_u32(Bs + r * AS2 + lc), T_g + (size_t)(col0 + r) * 512 + lc);
        }
        cp_commit();
    }

    int buf = 0;
    for (int kk = 0; kk < 512; kk += 32) {
        if (kk + 32 < 512) {
            __half* Ah = smh + (buf ^ 1) * 3 * TSZ;
            __half* Al = Ah + TSZ;
            __half* Bs = Al + TSZ;
            int kn = kk + 32;
#pragma unroll
            for (int half = 0; half < 2; half++) {
                int r = lr + half * 64;
                cp16(smem_u32(Ah + r * AS2 + lc),
                     Ah_g + (size_t)(row0 + r) * 512 + kn + lc);
                cp16(smem_u32(Al + r * AS2 + lc),
                     Al_g + (size_t)(row0 + r) * 512 + kn + lc);
                cp16(smem_u32(Bs + r * AS2 + lc),
                     T_g + (size_t)(col0 + r) * 512 + kn + lc);
            }
            cp_commit();
            cp_wait<1>();
        } else {
            cp_wait<0>();
        }
        __syncthreads();

        const __half* Ah = smh + buf * 3 * TSZ;
        const __half* Al = Ah + TSZ;
        const __half* Bs = Al + TSZ;
#pragma unroll
        for (int ks = 0; ks < 32; ks += 16) {
            uint32_t ah[4][4], al[4][4], b[4][2];
#pragma unroll
            for (int mf = 0; mf < 4; mf++) {
                int rb = wm * 64 + mf * 16 + g;
                ah[mf][0] = *(uint32_t*)&Ah[rb * AS2 + ks + t2];
                ah[mf][1] = *(uint32_t*)&Ah[(rb + 8) * AS2 + ks + t2];
                ah[mf][2] = *(uint32_t*)&Ah[rb * AS2 + ks + 8 + t2];
                ah[mf][3] = *(uint32_t*)&Ah[(rb + 8) * AS2 + ks + 8 + t2];
                al[mf][0] = *(uint32_t*)&Al[rb * AS2 + ks + t2];
                al[mf][1] = *(uint32_t*)&Al[(rb + 8) * AS2 + ks + t2];
                al[mf][2] = *(uint32_t*)&Al[rb * AS2 + ks + 8 + t2];
                al[mf][3] = *(uint32_t*)&Al[(rb + 8) * AS2 + ks + 8 + t2];
            }
#pragma unroll
            for (int nf = 0; nf < 4; nf++) {
                int cb = wn * 32 + nf * 8 + g;
                b[nf][0] = *(uint32_t*)&Bs[cb * AS2 + ks + t2];
                b[nf][1] = *(uint32_t*)&Bs[cb * AS2 + ks + 8 + t2];
            }
#pragma unroll
            for (int mf = 0; mf < 4; mf++)
#pragma unroll
                for (int nf = 0; nf < 4; nf++) {
                    mma_f16(acc[mf][nf], ah[mf][0], ah[mf][1], ah[mf][2],
                            ah[mf][3], b[nf][0], b[nf][1]);
                    mma_f16(acc[mf][nf], al[mf][0], al[mf][1], al[mf][2],
                            al[mf][3], b[nf][0], b[nf][1]);
                }
        }
        __syncthreads();
        buf ^= 1;
    }

#pragma unroll
    for (int mf = 0; mf < 4; mf++) {
#pragma unroll
        for (int nf = 0; nf < 4; nf++) {
            int rr = row0 + wm * 64 + mf * 16 + g;
            int cc = col0 + wn * 32 + nf * 8 + t2;
            *(float2*)&outF[(size_t)rr * 512 + cc] =
                make_float2(acc[mf][nf][0], acc[mf][nf][1]);
            *(float2*)&outF[(size_t)(rr + 8) * 512 + cc] =
                make_float2(acc[mf][nf][2], acc[mf][nf][3]);
        }
    }
}

// ---------------- fused banded attention (round-14 proven body) ----------------
// fp16-single Q/K/V: 1-pass QK, 1-pass QE, 1-pass PV; in-register fp16 P;
// warp-local online softmax, exact cross-warp merge at end; fp16 hi/lo C out.
__global__ void __launch_bounds__(256, 1) attn_tc13(
    const __half* __restrict__ Qg, const __half* __restrict__ Kg,
    const __half* __restrict__ Vth, const __half* __restrict__ Et,
    __half* __restrict__ Ch, __half* __restrict__ Cl) {
    constexpr int QS = 72, KS = 72, ES = 72, VS = 200, QES = 132, OS = 68;
    extern __shared__ char smraw[];
    __half* Qsh = (__half*)smraw;                // [64][QS]
    __half* Ksh = Qsh + 64 * QS;                 // [192][KS]
    __half* Esh = Ksh + 192 * KS;                // [128][ES]
    __half* Vsh = Esh + 128 * ES;                // [64][VS]
    float* QEs = (float*)(Vsh + 64 * VS);        // [64][QES] fp32
    float* mls = QEs + 64 * QES;                 // [4][64]
    float* lls = mls + 256;                      // [4][64]
    float* Ored = (float*)Ksh;                   // epilogue alias

    const int tid = threadIdx.x, lane = tid & 31, wid = tid >> 5;
    const int wm = wid >> 2, wn = wid & 3;  // 2 x 4 warps
    const int g = lane >> 2, t2 = (lane & 3) * 2;
    const int n = blockIdx.y, m0 = blockIdx.x * 64;
    const float SCl2 = 0.125f * 1.4426950408889634f;

    auto issue_KE = [&](int c) {
        const size_t kbase = ((size_t)n * 2048 + m0 + c * 128) << 6;
        const __half* sh = Kg + kbase;
#pragma unroll
        for (int it = 0; it < 6; it++) {
            int f = tid + it * 256;
            int kr = f >> 3, j = (f & 7) * 8;
            cp16(smem_u32(Ksh + kr * KS + j), sh + f * 8);
        }
        const __half* es = Et + (size_t)(c * 128) * 64;
#pragma unroll
        for (int it = 0; it < 4; it++) {
            int f = tid + it * 256;
            int s = f >> 3, j = (f & 7) * 8;
            cp16(smem_u32(Esh + s * ES + j), es + f * 8);
        }
    };
    auto issue_V = [&](int c) {
        const __half* vh = Vth + (size_t)n * 64 * 2048 + m0 + c * 128;
#pragma unroll
        for (int it = 0; it < 6; it++) {
            int f = tid + it * 256;
            int d = f / 24, j = f - d * 24;
            cp16(smem_u32(Vsh + d * VS + j * 8), vh + (size_t)d * 2048 + j * 8);
        }
    };

    // stage Q tile
    {
        const uint4* sh = (const uint4*)(Qg + (((size_t)n * 1024 + m0) << 6));
#pragma unroll
        for (int it = 0; it < 2; it++) {
            int f = tid + it * 256;
            int m = f >> 3, j = f & 7;
            ((uint4*)(Qsh + m * QS))[j] = sh[f];
        }
    }

    issue_KE(0);
    cp_commit();
    issue_V(0);
    cp_commit();

    float o[2][8][4] = {};
    float mreg[2][2] = {{-1e30f, -1e30f}, {-1e30f, -1e30f}};
    float lreg[2][2] = {};

    for (int c = 0; c < 8; c++) {
        cp_wait<1>();
        __syncthreads();

        // ---- fused QK (1 pass) + QE (1 pass) ----
        float sAcc[2][6][4] = {};
        float qeAcc[2][4][4] = {};
#pragma unroll
        for (int ks = 0; ks < 64; ks += 16) {
            uint32_t ah[2][4];
#pragma unroll
            for (int mf = 0; mf < 2; mf++) {
                int rb = wm * 32 + mf * 16 + g;
                ah[mf][0] = *(uint32_t*)&Qsh[rb * QS + ks + t2];
                ah[mf][1] = *(uint32_t*)&Qsh[(rb + 8) * QS + ks + t2];
                ah[mf][2] = *(uint32_t*)&Qsh[rb * QS + ks + 8 + t2];
                ah[mf][3] = *(uint32_t*)&Qsh[(rb + 8) * QS + ks + 8 + t2];
            }
#pragma unroll
            for (int nf = 0; nf < 6; nf++) {
                int cb = wn * 48 + nf * 8 + g;
                uint32_t kb0 = *(uint32_t*)&Ksh[cb * KS + ks + t2];
                uint32_t kb1 = *(uint32_t*)&Ksh[cb * KS + ks + 8 + t2];
#pragma unroll
                for (int mf = 0; mf < 2; mf++)
                    mma_f16(sAcc[mf][nf], ah[mf][0], ah[mf][1], ah[mf][2],
                            ah[mf][3], kb0, kb1);
            }
#pragma unroll
            for (int nf = 0; nf < 4; nf++) {
                int cb = wn * 32 + nf * 8 + g;
                uint32_t eb0 = *(uint32_t*)&Esh[cb * ES + ks + t2];
                uint32_t eb1 = *(uint32_t*)&Esh[cb * ES + ks + 8 + t2];
#pragma unroll
                for (int mf = 0; mf < 2; mf++)
                    mma_f16(qeAcc[mf][nf], ah[mf][0], ah[mf][1], ah[mf][2],
                            ah[mf][3], eb0, eb1);
            }
        }
#pragma unroll
        for (int mf = 0; mf < 2; mf++) {
            int R = wm * 32 + mf * 16 + g;
#pragma unroll
            for (int nf = 0; nf < 4; nf++) {
                int cc = wn * 32 + nf * 8 + t2;
                *(float2*)&QEs[R * QES + cc] =
                    make_float2(qeAcc[mf][nf][0], qeAcc[mf][nf][1]);
                *(float2*)&QEs[(R + 8) * QES + cc] =
                    make_float2(qeAcc[mf][nf][2], qeAcc[mf][nf][3]);
            }
        }
        __syncthreads();

        if (c < 7) issue_KE(c + 1);
        cp_commit();

        // ---- warp-local masked softmax ----
        uint32_t pf[2][3][4];
#pragma unroll
        for (int mf = 0; mf < 2; mf++) {
            int R = wm * 32 + mf * 16 + g;
            float mx0 = -3e38f, mx1 = -3e38f;
#pragma unroll
            for (int nf = 0; nf < 6; nf++) {
                int cc = wn * 48 + nf * 8 + t2;
#pragma unroll
                for (int e = 0; e < 4; e++) {
                    int r = R + ((e >> 1) << 3);
                    int col = cc + (e & 1);
                    int diff = col - r;
                    float z = -3e38f;
                    if ((unsigned)diff < 128u)
                        z = sAcc[mf][nf][e] + QEs[r * QES + diff];
                    sAcc[mf][nf][e] = z;
                    if (e < 2) mx0 = fmaxf(mx0, z);
                    else mx1 = fmaxf(mx1, z);
                }
            }
            mx0 = fmaxf(mx0, __shfl_xor_sync(0xffffffffu, mx0, 1));
            mx0 = fmaxf(mx0, __shfl_xor_sync(0xffffffffu, mx0, 2));
            mx1 = fmaxf(mx1, __shfl_xor_sync(0xffffffffu, mx1, 1));
            mx1 = fmaxf(mx1, __shfl_xor_sync(0xffffffffu, mx1, 2));
            float mn0 = fmaxf(mreg[mf][0], mx0 * SCl2);
            float mn1 = fmaxf(mreg[mf][1], mx1 * SCl2);
            float al0 = exp2f(mreg[mf][0] - mn0);
            float al1 = exp2f(mreg[mf][1] - mn1);
            float sum0 = 0.f, sum1 = 0.f;
#pragma unroll
            for (int nf = 0; nf < 6; nf++) {
                float p0 = exp2f(sAcc[mf][nf][0] * SCl2 - mn0);
                float p1 = exp2f(sAcc[mf][nf][1] * SCl2 - mn0);
                float p2 = exp2f(sAcc[mf][nf][2] * SCl2 - mn1);
                float p3 = exp2f(sAcc[mf][nf][3] * SCl2 - mn1);
                sum0 += p0 + p1;
                sum1 += p2 + p3;
                int k = nf >> 1, hf = (nf & 1) * 2;
                pf[mf][k][hf + 0] = pack_h2(p0, p1);
                pf[mf][k][hf + 1] = pack_h2(p2, p3);
            }
            sum0 += __shfl_xor_sync(0xffffffffu, sum0, 1);
            sum0 += __shfl_xor_sync(0xffffffffu, sum0, 2);
            sum1 += __shfl_xor_sync(0xffffffffu, sum1, 1);
            sum1 += __shfl_xor_sync(0xffffffffu, sum1, 2);
            lreg[mf][0] = lreg[mf][0] * al0 + sum0;
            lreg[mf][1] = lreg[mf][1] * al1 + sum1;
            mreg[mf][0] = mn0;
            mreg[mf][1] = mn1;
#pragma unroll
            for (int nfd = 0; nfd < 8; nfd++) {
                o[mf][nfd][0] *= al0;
                o[mf][nfd][1] *= al0;
                o[mf][nfd][2] *= al1;
                o[mf][nfd][3] *= al1;
            }
        }
        cp_wait<1>();
        __syncthreads();

        // ---- PV: 1 pass fp16 ----
#pragma unroll
        for (int k = 0; k < 3; k++) {
            int ks = wn * 48 + k * 16;
#pragma unroll
            for (int nfd = 0; nfd < 8; nfd++) {
                int cb = nfd * 8 + g;
                uint32_t vh0 = *(uint32_t*)&Vsh[cb * VS + ks + t2];
                uint32_t vh1 = *(uint32_t*)&Vsh[cb * VS + ks + 8 + t2];
#pragma unroll
                for (int mf = 0; mf < 2; mf++)
                    mma_f16(o[mf][nfd], pf[mf][k][0], pf[mf][k][1],
                            pf[mf][k][2], pf[mf][k][3], vh0, vh1);
            }
        }
        __syncthreads();

        if (c < 7) issue_V(c + 1);
        cp_commit();
    }

    // ---- epilogue: cross-warp merge + normalize + store (fp16 hi/lo) ----
    {
        int wbase = (wm * 4 + wn) * 32;
#pragma unroll
        for (int mf = 0; mf < 2; mf++) {
            int lr0 = mf * 16 + g;
            if ((lane & 3) == 0) {
                mls[wn * 64 + wm * 32 + lr0] = mreg[mf][0];
                mls[wn * 64 + wm * 32 + lr0 + 8] = mreg[mf][1];
                lls[wn * 64 + wm * 32 + lr0] = lreg[mf][0];
                lls[wn * 64 + wm * 32 + lr0 + 8] = lreg[mf][1];
            }
#pragma unroll
            for (int nfd = 0; nfd < 8; nfd++) {
                int cc = nfd * 8 + t2;
                *(float2*)&Ored[(wbase + lr0) * OS + cc] =
                    make_float2(o[mf][nfd][0], o[mf][nfd][1]);
                *(float2*)&Ored[(wbase + lr0 + 8) * OS + cc] =
                    make_float2(o[mf][nfd][2], o[mf][nfd][3]);
            }
        }
    }
    __syncthreads();
    {
        const int b = n >> 3, kh = n & 7;
#pragma unroll
        for (int u = 0; u < 4; u++) {
            int id = tid + u * 256;
            int r = id >> 4;
            int c4 = (id & 15) * 4;
            int wmr = r >> 5, lr = r & 31;
            float mw0 = mls[r], mw1 = mls[64 + r], mw2 = mls[128 + r],
                  mw3 = mls[192 + r];
            float ms = fmaxf(fmaxf(mw0, mw1), fmaxf(mw2, mw3));
            float e0 = exp2f(mw0 - ms), e1 = exp2f(mw1 - ms),
                  e2 = exp2f(mw2 - ms), e3 = exp2f(mw3 - ms);
            float lt = lls[r] * e0 + lls[64 + r] * e1 + lls[128 + r] * e2 +
                       lls[192 + r] * e3;
            float4 s0 = *(float4*)&Ored[((wmr * 4 + 0) * 32 + lr) * OS + c4];
            float4 s1 = *(float4*)&Ored[((wmr * 4 + 1) * 32 + lr) * OS + c4];
            float4 s2 = *(float4*)&Ored[((wmr * 4 + 2) * 32 + lr) * OS + c4];
            float4 s3 = *(float4*)&Ored[((wmr * 4 + 3) * 32 + lr) * OS + c4];
            float inv = 1.0f / lt;
            float x = (s0.x * e0 + s1.x * e1 + s2.x * e2 + s3.x * e3) * inv;
            float y = (s0.y * e0 + s1.y * e1 + s2.y * e2 + s3.y * e3) * inv;
            float z = (s0.z * e0 + s1.z * e1 + s2.z * e2 + s3.z * e3) * inv;
            float w = (s0.w * e0 + s1.w * e1 + s2.w * e2 + s3.w * e3) * inv;
            __half h0, l0, h1, l1, h2, l2, h3, l3;
            split_h(x, h0, l0);
            split_h(y, h1, l1);
            split_h(z, h2, l2);
            split_h(w, h3, l3);
            size_t base = ((size_t)b * 1024 + m0 + r) * 512 + kh * 64 + c4;
            st_h2(&Ch[base], h0, h1);
            st_h2(&Ch[base + 2], h2, h3);
            st_h2(&Cl[base], l0, l1);
            st_h2(&Cl[base + 2], l2, l3);
        }
    }
}

// ---------------- launcher ----------------------------------------------------
extern "C" void kernel_launch(void* const* d_in, const int* in_sizes, int n_in,
                              void* d_out, int out_size) {
    const float* query = (const float*)d_in[0];
    const float* key = (const float*)d_in[1];
    const float* value = (const float*)d_in[2];
    const float* pos = (const float*)d_in[3];
    const float* Wq = (const float*)d_in[4];
    const float* Wk = (const float*)d_in[5];
    const float* Wv = (const float*)d_in[6];
    const float* Wo = (const float*)d_in[7];
    float* out = (float*)d_out;

    __half *qg, *kg, *vh, *vth, *et;
    __half *xq, *xk, *xv, *wqt, *wkt, *wvt, *wot, *ch, *cl;
    cudaGetSymbolAddress((void**)&qg, g_Qh);
    cudaGetSymbolAddress((void**)&kg, g_Kh);
    cudaGetSymbolAddress((void**)&vh, g_Vh);
    cudaGetSymbolAddress((void**)&vth, g_Vth);
    cudaGetSymbolAddress((void**)&et, g_Et);
    cudaGetSymbolAddress((void**)&xq, g_Xq16);
    cudaGetSymbolAddress((void**)&xk, g_Xk16);
    cudaGetSymbolAddress((void**)&xv, g_Xv16);
    cudaGetSymbolAddress((void**)&wqt, g_WqT16);
    cudaGetSymbolAddress((void**)&wkt, g_WkT16);
    cudaGetSymbolAddress((void**)&wvt, g_WvT16);
    cudaGetSymbolAddress((void**)&wot, g_WoT16);
    cudaGetSymbolAddress((void**)&ch, g_Ch);
    cudaGetSymbolAddress((void**)&cl, g_Cl);

    // prep
    conv_x<<<4096, 256>>>(query, xq, 1048576);
    conv_x<<<8192, 256>>>(key, xk, 2097152);
    conv_x<<<8192, 256>>>(value, xv, 2097152);
    conv_wT_h<<<dim3(16, 16), 256>>>(Wq, wqt);
    conv_wT_h<<<dim3(16, 16), 256>>>(Wk, wkt);
    conv_wT_h<<<dim3(16, 16), 256>>>(Wv, wvt);
    conv_wT_h<<<dim3(16, 16), 256>>>(Wo, wot);
    conv_eT<<<dim3(32, 2), 256>>>(pos, et);

    // projections (single-pass fp16)
    const int hsm = 2 * 2 * TSZ * 2;  // 40960 bytes
    cudaFuncSetAttribute(gemm_h16, cudaFuncAttributeMaxDynamicSharedMemorySize,
                         hsm);
    gemm_h16<<<dim3(64, 4), 256, hsm>>>(xq, wqt, qg, 1024);
    gemm_h16<<<dim3(128, 4), 256, hsm>>>(xk, wkt, kg, 2048);
    gemm_h16<<<dim3(128, 4), 256, hsm>>>(xv, wvt, vh, 2048);

    // V transpose to [n][d][t]
    transpose_v<<<dim3(64, 2, 64), 256>>>((const uint16_t*)vh, (uint16_t*)vth);

    // attention (round-14 body, fp16 C out)
    const int smem_bytes =
        (64 * 72 + 192 * 72 + 128 * 72 + 64 * 200) * 2 +
        (64 * 132 + 256 + 256) * 4;  // 115200
    cudaFuncSetAttribute(attn_tc13, cudaFuncAttributeMaxDynamicSharedMemorySize,
                         smem_bytes);
    attn_tc13<<<dim3(16, 64), 256, smem_bytes>>>(qg, kg, vth, et, ch, cl);

    // output projection (2-pass fp16)
    const int osm = 2 * 3 * TSZ * 2;  // 61440 bytes
    cudaFuncSetAttribute(gemm_out2, cudaFuncAttributeMaxDynamicSharedMemorySize,
                         osm);
    gemm_out2<<<dim3(64, 4), 256, osm>>>(ch, cl, wot, out);
}

// round 17
// speedup vs baseline: 1.2391x; 1.0394x over previous
#include <cuda_runtime.h>
#include <cuda_bf16.h>
#include <cuda_fp16.h>
#include <stdint.h>
#include <math.h>

// B=8, M=1024, H=512, K=8 heads, D=64, SPAN=1024, MK=2048
#define DINLINE __device__ __forceinline__

// ---------------- scratch ----------------------------------------------------
__device__ __align__(16) __half g_Qh[64 * 1024 * 64];
__device__ __align__(16) __half g_Kh[64 * 2048 * 64];
__device__ __align__(16) __half g_Vth[64 * 64 * 2048];   // V^T [n][d][t]
__device__ __align__(16) __half g_Et[1024 * 64];         // E^T [s][d]
__device__ __align__(16) __half g_Xq16[8 * 1024 * 512];
__device__ __align__(16) __half g_Xk16[8 * 2048 * 512];
__device__ __align__(16) __half g_Xv16[8 * 2048 * 512];
__device__ __align__(16) __half g_WqT16[512 * 512];
__device__ __align__(16) __half g_WkT16[512 * 512];
__device__ __align__(16) __half g_WvT16[512 * 512];
__device__ __align__(16) __half g_WoT16[512 * 512];
__device__ __align__(16) __half g_Ch[8 * 1024 * 512], g_Cl[8 * 1024 * 512];

// ---------------- helpers ----------------------------------------------------
DINLINE void mma_f16(float c[4], uint32_t a0, uint32_t a1, uint32_t a2,
                     uint32_t a3, uint32_t b0, uint32_t b1) {
    asm volatile(
        "mma.sync.aligned.m16n8k16.row.col.f32.f16.f16.f32 "
        "{%0,%1,%2,%3}, {%4,%5,%6,%7}, {%8,%9}, {%0,%1,%2,%3};\n"
        : "+f"(c[0]), "+f"(c[1]), "+f"(c[2]), "+f"(c[3])
        : "r"(a0), "r"(a1), "r"(a2), "r"(a3), "r"(b0), "r"(b1));
}

DINLINE uint32_t smem_u32(const void* p) {
    return (uint32_t)__cvta_generic_to_shared(p);
}

DINLINE void cp16(uint32_t dst, const void* src) {
    asm volatile("cp.async.cg.shared.global [%0], [%1], 16;\n" ::"r"(dst),
                 "l"(src));
}
DINLINE void cp_commit() { asm volatile("cp.async.commit_group;\n" ::); }
template <int N>
DINLINE void cp_wait() {
    asm volatile("cp.async.wait_group %0;\n" ::"n"(N));
}

DINLINE void split_h(float x, __half& h, __half& l) {
    h = __float2half_rn(x);
    l = __float2half_rn(x - __half2float(h));
}

DINLINE void st_h2(__half* p, __half a, __half b) {
    __half2 t;
    t.x = a;
    t.y = b;
    *(__half2*)p = t;
}

DINLINE uint32_t pack_h2(float a, float b) {
    __half2 t = __floats2half2_rn(a, b);
    return *(uint32_t*)&t;
}

// ---------------- merged prep kernels ------------------------------------------
// Q (1048576 f4) + K (2097152 f4) + V (2097152 f4) -> fp16, one launch
__global__ void __launch_bounds__(256) conv_x_all(
    const float* __restrict__ q, const float* __restrict__ k,
    const float* __restrict__ v, __half* __restrict__ xq,
    __half* __restrict__ xk, __half* __restrict__ xv) {
    int i = blockIdx.x * blockDim.x + threadIdx.x;  // < 5242880
    const float* src;
    __half* dst;
    int off;
    if (i < 1048576) {
        src = q; dst = xq; off = i;
    } else if (i < 3145728) {
        src = k; dst = xk; off = i - 1048576;
    } else {
        src = v; dst = xv; off = i - 3145728;
    }
    float4 val = ((const float4*)src)[off];
    ((__half2*)dst)[off * 2] = __floats2half2_rn(val.x, val.y);
    ((__half2*)dst)[off * 2 + 1] = __floats2half2_rn(val.z, val.w);
}

// z<4: W[z][k][n] fp32 -> T[n][k] fp16 ; z==4: E [d][s] -> E^T [s][d]
__global__ void __launch_bounds__(256) conv_wE_all(
    const float* __restrict__ Wq, const float* __restrict__ Wk,
    const float* __restrict__ Wv, const float* __restrict__ Wo,
    const float* __restrict__ E, __half* __restrict__ Tq,
    __half* __restrict__ Tk, __half* __restrict__ Tv,
    __half* __restrict__ To, __half* __restrict__ Et) {
    __shared__ float tile[32][33];
    int tx = threadIdx.x & 31, ty = threadIdx.x >> 5;  // 32 x 8
    int z = blockIdx.z;
    if (z < 4) {
        const float* W = (z == 0) ? Wq : (z == 1) ? Wk : (z == 2) ? Wv : Wo;
        __half* T = (z == 0) ? Tq : (z == 1) ? Tk : (z == 2) ? Tv : To;
        int n0 = blockIdx.x * 32, k0 = blockIdx.y * 32;
#pragma unroll
        for (int i = 0; i < 4; i++)
            tile[ty + i * 8][tx] = W[(size_t)(k0 + ty + i * 8) * 512 + n0 + tx];
        __syncthreads();
#pragma unroll
        for (int i = 0; i < 4; i++)
            T[(size_t)(n0 + ty + i * 8) * 512 + k0 + tx] =
                __float2half_rn(tile[tx][ty + i * 8]);
    } else {
        int idx = blockIdx.x + blockIdx.y * 16;  // 0..255, need 64
        if (idx >= 64) return;
        int s0 = (idx & 31) * 32, d0 = (idx >> 5) * 32;
#pragma unroll
        for (int i = 0; i < 4; i++)
            tile[ty + i * 8][tx] = E[(size_t)(d0 + ty + i * 8) * 1024 + s0 + tx];
        __syncthreads();
#pragma unroll
        for (int i = 0; i < 4; i++)
            Et[(size_t)(s0 + ty + i * 8) * 64 + d0 + tx] =
                __float2half_rn(tile[tx][ty + i * 8]);
    }
}

// ---------------- single-pass fp16 GEMM (Q/K/V projections) -------------------
// EPI=0: head-scatter [n][t][d] fp16. EPI=1: V^T scatter [n][d][t] fp16.
constexpr int AS2 = 40;
constexpr int TSZ = 128 * AS2;

template <int EPI>
__global__ void __launch_bounds__(256, 1) gemm_h16(
    const __half* __restrict__ A_g, const __half* __restrict__ T_g,
    __half* __restrict__ outH, int T) {
    extern __shared__ __half smh[];

    const int tid = threadIdx.x;
    const int lane = tid & 31, wid = tid >> 5;
    const int wm = wid >> 2, wn = wid & 3;
    const int row0 = blockIdx.x * 128, col0 = blockIdx.y * 128;
    const int g = lane >> 2, t2 = (lane & 3) * 2;
    const int lr = tid >> 2;
    const int lc = (tid & 3) * 8;

    float acc[4][4][4] = {};

    {
        __half* As = smh;
        __half* Bs = As + TSZ;
#pragma unroll
        for (int half = 0; half < 2; half++) {
            int r = lr + half * 64;
            cp16(smem_u32(As + r * AS2 + lc), A_g + (size_t)(row0 + r) * 512 + lc);
            cp16(smem_u32(Bs + r * AS2 + lc), T_g + (size_t)(col0 + r) * 512 + lc);
        }
        cp_commit();
    }

    int buf = 0;
    for (int kk = 0; kk < 512; kk += 32) {
        if (kk + 32 < 512) {
            __half* As = smh + (buf ^ 1) * 2 * TSZ;
            __half* Bs = As + TSZ;
            int kn = kk + 32;
#pragma unroll
            for (int half = 0; half < 2; half++) {
                int r = lr + half * 64;
                cp16(smem_u32(As + r * AS2 + lc),
                     A_g + (size_t)(row0 + r) * 512 + kn + lc);
                cp16(smem_u32(Bs + r * AS2 + lc),
                     T_g + (size_t)(col0 + r) * 512 + kn + lc);
            }
            cp_commit();
            cp_wait<1>();
        } else {
            cp_wait<0>();
        }
        __syncthreads();

        const __half* As = smh + buf * 2 * TSZ;
        const __half* Bs = As + TSZ;
#pragma unroll
        for (int ks = 0; ks < 32; ks += 16) {
            uint32_t a[4][4], b[4][2];
#pragma unroll
            for (int mf = 0; mf < 4; mf++) {
                int rb = wm * 64 + mf * 16 + g;
                a[mf][0] = *(uint32_t*)&As[rb * AS2 + ks + t2];
                a[mf][1] = *(uint32_t*)&As[(rb + 8) * AS2 + ks + t2];
                a[mf][2] = *(uint32_t*)&As[rb * AS2 + ks + 8 + t2];
                a[mf][3] = *(uint32_t*)&As[(rb + 8) * AS2 + ks + 8 + t2];
            }
#pragma unroll
            for (int nf = 0; nf < 4; nf++) {
                int cb = wn * 32 + nf * 8 + g;
                b[nf][0] = *(uint32_t*)&Bs[cb * AS2 + ks + t2];
                b[nf][1] = *(uint32_t*)&Bs[cb * AS2 + ks + 8 + t2];
            }
#pragma unroll
            for (int mf = 0; mf < 4; mf++)
#pragma unroll
                for (int nf = 0; nf < 4; nf++)
                    mma_f16(acc[mf][nf], a[mf][0], a[mf][1], a[mf][2],
                            a[mf][3], b[nf][0], b[nf][1]);
        }
        __syncthreads();
        buf ^= 1;
    }

#pragma unroll
    for (int mf = 0; mf < 4; mf++) {
#pragma unroll
        for (int nf = 0; nf < 4; nf++) {
            int rr = row0 + wm * 64 + mf * 16 + g;
            int cc = col0 + wn * 32 + nf * 8 + t2;
            int head = cc >> 6, d = cc & 63;
#pragma unroll
            for (int rh = 0; rh < 2; rh++) {
                int grow = rr + rh * 8;
                int b = grow / T, t = grow - b * T;
                int n = b * 8 + head;
                if (EPI == 0) {
                    size_t idx = (((size_t)n * T + t) << 6) + d;
                    st_h2(outH + idx, __float2half_rn(acc[mf][nf][rh * 2 + 0]),
                          __float2half_rn(acc[mf][nf][rh * 2 + 1]));
                } else {
                    // V^T [n][d][t] direct scatter
                    size_t base = ((size_t)n * 64 + d) * 2048 + t;
                    outH[base] = __float2half_rn(acc[mf][nf][rh * 2 + 0]);
                    outH[base + 2048] = __float2half_rn(acc[mf][nf][rh * 2 + 1]);
                }
            }
        }
    }
}

// ---------------- 2-pass fp16 GEMM for output projection -----------------------
__global__ void __launch_bounds__(256, 1) gemm_out2(
    const __half* __restrict__ Ah_g, const __half* __restrict__ Al_g,
    const __half* __restrict__ T_g, float* __restrict__ outF) {
    extern __shared__ __half smh[];

    const int tid = threadIdx.x;
    const int lane = tid & 31, wid = tid >> 5;
    const int wm = wid >> 2, wn = wid & 3;
    const int row0 = blockIdx.x * 128, col0 = blockIdx.y * 128;
    const int g = lane >> 2, t2 = (lane & 3) * 2;
    const int lr = tid >> 2;
    const int lc = (tid & 3) * 8;

    float acc[4][4][4] = {};

    {
        __half* Ah = smh;
        __half* Al = Ah + TSZ;
        __half* Bs = Al + TSZ;
#pragma unroll
        for (int half = 0; half < 2; half++) {
            int r = lr + half * 64;
            cp16(smem_u32(Ah + r * AS2 + lc), Ah_g + (size_t)(row0 + r) * 512 + lc);
            cp16(smem_u32(Al + r * AS2 + lc), Al_g + (size_t)(row0 + r) * 512 + lc);
            cp16(smem_u32(Bs + r * AS2 + lc), T_g + (size_t)(col0 + r) * 512 + lc);
        }
        cp_commit();
    }

    int buf = 0;
    for (int kk = 0; kk < 512; kk += 32) {
        if (kk + 32 < 512) {
            __half* Ah = smh + (buf ^ 1) * 3 * TSZ;
            __half* Al = Ah + TSZ;
            __half* Bs = Al + TSZ;
            int kn = kk + 32;
#pragma unroll
            for (int half = 0; half < 2; half++) {
                int r = lr + half * 64;
                cp16(smem_u32(Ah + r * AS2 + lc),
                     Ah_g + (size_t)(row0 + r) * 512 + kn + lc);
                cp16(smem_u32(Al + r * AS2 + lc),
                     Al_g + (size_t)(row0 + r) * 512 + kn + lc);
                cp16(smem_u32(Bs + r * AS2 + lc),
                     T_g + (size_t)(col0 + r) * 512 + kn + lc);
            }
            cp_commit();
            cp_wait<1>();
        } else {
            cp_wait<0>();
        }
        __syncthreads();

        const __half* Ah = smh + buf * 3 * TSZ;
        const __half* Al = Ah + TSZ;
        const __half* Bs = Al + TSZ;
#pragma unroll
        for (int ks = 0; ks < 32; ks += 16) {
            uint32_t ah[4][4], al[4][4], b[4][2];
#pragma unroll
            for (int mf = 0; mf < 4; mf++) {
                int rb = wm * 64 + mf * 16 + g;
                ah[mf][0] = *(uint32_t*)&Ah[rb * AS2 + ks + t2];
                ah[mf][1] = *(uint32_t*)&Ah[(rb + 8) * AS2 + ks + t2];
                ah[mf][2] = *(uint32_t*)&Ah[rb * AS2 + ks + 8 + t2];
                ah[mf][3] = *(uint32_t*)&Ah[(rb + 8) * AS2 + ks + 8 + t2];
                al[mf][0] = *(uint32_t*)&Al[rb * AS2 + ks + t2];
                al[mf][1] = *(uint32_t*)&Al[(rb + 8) * AS2 + ks + t2];
                al[mf][2] = *(uint32_t*)&Al[rb * AS2 + ks + 8 + t2];
                al[mf][3] = *(uint32_t*)&Al[(rb + 8) * AS2 + ks + 8 + t2];
            }
#pragma unroll
            for (int nf = 0; nf < 4; nf++) {
                int cb = wn * 32 + nf * 8 + g;
                b[nf][0] = *(uint32_t*)&Bs[cb * AS2 + ks + t2];
                b[nf][1] = *(uint32_t*)&Bs[cb * AS2 + ks + 8 + t2];
            }
#pragma unroll
            for (int mf = 0; mf < 4; mf++)
#pragma unroll
                for (int nf = 0; nf < 4; nf++) {
                    mma_f16(acc[mf][nf], ah[mf][0], ah[mf][1], ah[mf][2],
                            ah[mf][3], b[nf][0], b[nf][1]);
                    mma_f16(acc[mf][nf], al[mf][0], al[mf][1], al[mf][2],
                            al[mf][3], b[nf][0], b[nf][1]);
                }
        }
        __syncthreads();
        buf ^= 1;
    }

#pragma unroll
    for (int mf = 0; mf < 4; mf++) {
#pragma unroll
        for (int nf = 0; nf < 4; nf++) {
            int rr = row0 + wm * 64 + mf * 16 + g;
            int cc = col0 + wn * 32 + nf * 8 + t2;
            *(float2*)&outF[(size_t)rr * 512 + cc] =
                make_float2(acc[mf][nf][0], acc[mf][nf][1]);
            *(float2*)&outF[(size_t)(rr + 8) * 512 + cc] =
                make_float2(acc[mf][nf][2], acc[mf][nf][3]);
        }
    }
}

// ---------------- fused banded attention (round-16 proven body) ----------------
__global__ void __launch_bounds__(256, 1) attn_tc13(
    const __half* __restrict__ Qg, const __half* __restrict__ Kg,
    const __half* __restrict__ Vth, const __half* __restrict__ Et,
    __half* __restrict__ Ch, __half* __restrict__ Cl) {
    constexpr int QS = 72, KS = 72, ES = 72, VS = 200, QES = 132, OS = 68;
    extern __shared__ char smraw[];
    __half* Qsh = (__half*)smraw;                // [64][QS]
    __half* Ksh = Qsh + 64 * QS;                 // [192][KS]
    __half* Esh = Ksh + 192 * KS;                // [128][ES]
    __half* Vsh = Esh + 128 * ES;                // [64][VS]
    float* QEs = (float*)(Vsh + 64 * VS);        // [64][QES] fp32
    float* mls = QEs + 64 * QES;                 // [4][64]
    float* lls = mls + 256;                      // [4][64]
    float* Ored = (float*)Ksh;                   // epilogue alias

    const int tid = threadIdx.x, lane = tid & 31, wid = tid >> 5;
    const int wm = wid >> 2, wn = wid & 3;  // 2 x 4 warps
    const int g = lane >> 2, t2 = (lane & 3) * 2;
    const int n = blockIdx.y, m0 = blockIdx.x * 64;
    const float SCl2 = 0.125f * 1.4426950408889634f;

    auto issue_KE = [&](int c) {
        const size_t kbase = ((size_t)n * 2048 + m0 + c * 128) << 6;
        const __half* sh = Kg + kbase;
#pragma unroll
        for (int it = 0; it < 6; it++) {
            int f = tid + it * 256;
            int kr = f >> 3, j = (f & 7) * 8;
            cp16(smem_u32(Ksh + kr * KS + j), sh + f * 8);
        }
        const __half* es = Et + (size_t)(c * 128) * 64;
#pragma unroll
        for (int it = 0; it < 4; it++) {
            int f = tid + it * 256;
            int s = f >> 3, j = (f & 7) * 8;
            cp16(smem_u32(Esh + s * ES + j), es + f * 8);
        }
    };
    auto issue_V = [&](int c) {
        const __half* vh = Vth + (size_t)n * 64 * 2048 + m0 + c * 128;
#pragma unroll
        for (int it = 0; it < 6; it++) {
            int f = tid + it * 256;
            int d = f / 24, j = f - d * 24;
            cp16(smem_u32(Vsh + d * VS + j * 8), vh + (size_t)d * 2048 + j * 8);
        }
    };

    // stage Q tile
    {
        const uint4* sh = (const uint4*)(Qg + (((size_t)n * 1024 + m0) << 6));
#pragma unroll
        for (int it = 0; it < 2; it++) {
            int f = tid + it * 256;
            int m = f >> 3, j = f & 7;
            ((uint4*)(Qsh + m * QS))[j] = sh[f];
        }
    }

    issue_KE(0);
    cp_commit();
    issue_V(0);
    cp_commit();

    float o[2][8][4] = {};
    float mreg[2][2] = {{-1e30f, -1e30f}, {-1e30f, -1e30f}};
    float lreg[2][2] = {};

    for (int c = 0; c < 8; c++) {
        cp_wait<1>();
        __syncthreads();

        // ---- fused QK (1 pass) + QE (1 pass) ----
        float sAcc[2][6][4] = {};
        float qeAcc[2][4][4] = {};
#pragma unroll
        for (int ks = 0; ks < 64; ks += 16) {
            uint32_t ah[2][4];
#pragma unroll
            for (int mf = 0; mf < 2; mf++) {
                int rb = wm * 32 + mf * 16 + g;
                ah[mf][0] = *(uint32_t*)&Qsh[rb * QS + ks + t2];
                ah[mf][1] = *(uint32_t*)&Qsh[(rb + 8) * QS + ks + t2];
                ah[mf][2] = *(uint32_t*)&Qsh[rb * QS + ks + 8 + t2];
                ah[mf][3] = *(uint32_t*)&Qsh[(rb + 8) * QS + ks + 8 + t2];
            }
#pragma unroll
            for (int nf = 0; nf < 6; nf++) {
                int cb = wn * 48 + nf * 8 + g;
                uint32_t kb0 = *(uint32_t*)&Ksh[cb * KS + ks + t2];
                uint32_t kb1 = *(uint32_t*)&Ksh[cb * KS + ks + 8 + t2];
#pragma unroll
                for (int mf = 0; mf < 2; mf++)
                    mma_f16(sAcc[mf][nf], ah[mf][0], ah[mf][1], ah[mf][2],
                            ah[mf][3], kb0, kb1);
            }
#pragma unroll
            for (int nf = 0; nf < 4; nf++) {
                int cb = wn * 32 + nf * 8 + g;
                uint32_t eb0 = *(uint32_t*)&Esh[cb * ES + ks + t2];
                uint32_t eb1 = *(uint32_t*)&Esh[cb * ES + ks + 8 + t2];
#pragma unroll
                for (int mf = 0; mf < 2; mf++)
                    mma_f16(qeAcc[mf][nf], ah[mf][0], ah[mf][1], ah[mf][2],
                            ah[mf][3], eb0, eb1);
            }
        }
#pragma unroll
        for (int mf = 0; mf < 2; mf++) {
            int R = wm * 32 + mf * 16 + g;
#pragma unroll
            for (int nf = 0; nf < 4; nf++) {
                int cc = wn * 32 + nf * 8 + t2;
                *(float2*)&QEs[R * QES + cc] =
                    make_float2(qeAcc[mf][nf][0], qeAcc[mf][nf][1]);
                *(float2*)&QEs[(R + 8) * QES + cc] =
                    make_float2(qeAcc[mf][nf][2], qeAcc[mf][nf][3]);
            }
        }
        __syncthreads();

        if (c < 7) issue_KE(c + 1);
        cp_commit();

        // ---- warp-local masked softmax ----
        uint32_t pf[2][3][4];
#pragma unroll
        for (int mf = 0; mf < 2; mf++) {
            int R = wm * 32 + mf * 16 + g;
            float mx0 = -3e38f, mx1 = -3e38f;
#pragma unroll
            for (int nf = 0; nf < 6; nf++) {
                int cc = wn * 48 + nf * 8 + t2;
#pragma unroll
                for (int e = 0; e < 4; e++) {
                    int r = R + ((e >> 1) << 3);
                    int col = cc + (e & 1);
                    int diff = col - r;
                    float z = -3e38f;
                    if ((unsigned)diff < 128u)
                        z = sAcc[mf][nf][e] + QEs[r * QES + diff];
                    sAcc[mf][nf][e] = z;
                    if (e < 2) mx0 = fmaxf(mx0, z);
                    else mx1 = fmaxf(mx1, z);
                }
            }
            mx0 = fmaxf(mx0, __shfl_xor_sync(0xffffffffu, mx0, 1));
            mx0 = fmaxf(mx0, __shfl_xor_sync(0xffffffffu, mx0, 2));
            mx1 = fmaxf(mx1, __shfl_xor_sync(0xffffffffu, mx1, 1));
            mx1 = fmaxf(mx1, __shfl_xor_sync(0xffffffffu, mx1, 2));
            float mn0 = fmaxf(mreg[mf][0], mx0 * SCl2);
            float mn1 = fmaxf(mreg[mf][1], mx1 * SCl2);
            float al0 = exp2f(mreg[mf][0] - mn0);
            float al1 = exp2f(mreg[mf][1] - mn1);
            float sum0 = 0.f, sum1 = 0.f;
#pragma unroll
            for (int nf = 0; nf < 6; nf++) {
                float p0 = exp2f(sAcc[mf][nf][0] * SCl2 - mn0);
                float p1 = exp2f(sAcc[mf][nf][1] * SCl2 - mn0);
                float p2 = exp2f(sAcc[mf][nf][2] * SCl2 - mn1);
                float p3 = exp2f(sAcc[mf][nf][3] * SCl2 - mn1);
                sum0 += p0 + p1;
                sum1 += p2 + p3;
                int k = nf >> 1, hf = (nf & 1) * 2;
                pf[mf][k][hf + 0] = pack_h2(p0, p1);
                pf[mf][k][hf + 1] = pack_h2(p2, p3);
            }
            sum0 += __shfl_xor_sync(0xffffffffu, sum0, 1);
            sum0 += __shfl_xor_sync(0xffffffffu, sum0, 2);
            sum1 += __shfl_xor_sync(0xffffffffu, sum1, 1);
            sum1 += __shfl_xor_sync(0xffffffffu, sum1, 2);
            lreg[mf][0] = lreg[mf][0] * al0 + sum0;
            lreg[mf][1] = lreg[mf][1] * al1 + sum1;
            mreg[mf][0] = mn0;
            mreg[mf][1] = mn1;
#pragma unroll
            for (int nfd = 0; nfd < 8; nfd++) {
                o[mf][nfd][0] *= al0;
                o[mf][nfd][1] *= al0;
                o[mf][nfd][2] *= al1;
                o[mf][nfd][3] *= al1;
            }
        }
        cp_wait<1>();
        __syncthreads();

        // ---- PV: 1 pass fp16 ----
#pragma unroll
        for (int k = 0; k < 3; k++) {
            int ks = wn * 48 + k * 16;
#pragma unroll
            for (int nfd = 0; nfd < 8; nfd++) {
                int cb = nfd * 8 + g;
                uint32_t vh0 = *(uint32_t*)&Vsh[cb * VS + ks + t2];
                uint32_t vh1 = *(uint32_t*)&Vsh[cb * VS + ks + 8 + t2];
#pragma unroll
                for (int mf = 0; mf < 2; mf++)
                    mma_f16(o[mf][nfd], pf[mf][k][0], pf[mf][k][1],
                            pf[mf][k][2], pf[mf][k][3], vh0, vh1);
            }
        }
        __syncthreads();

        if (c < 7) issue_V(c + 1);
        cp_commit();
    }

    // ---- epilogue: cross-warp merge + normalize + store (fp16 hi/lo) ----
    {
        int wbase = (wm * 4 + wn) * 32;
#pragma unroll
        for (int mf = 0; mf < 2; mf++) {
            int lr0 = mf * 16 + g;
            if ((lane & 3) == 0) {
                mls[wn * 64 + wm * 32 + lr0] = mreg[mf][0];
                mls[wn * 64 + wm * 32 + lr0 + 8] = mreg[mf][1];
                lls[wn * 64 + wm * 32 + lr0] = lreg[mf][0];
                lls[wn * 64 + wm * 32 + lr0 + 8] = lreg[mf][1];
            }
#pragma unroll
            for (int nfd = 0; nfd < 8; nfd++) {
                int cc = nfd * 8 + t2;
                *(float2*)&Ored[(wbase + lr0) * OS + cc] =
                    make_float2(o[mf][nfd][0], o[mf][nfd][1]);
                *(float2*)&Ored[(wbase + lr0 + 8) * OS + cc] =
                    make_float2(o[mf][nfd][2], o[mf][nfd][3]);
            }
        }
    }
    __syncthreads();
    {
        const int b = n >> 3, kh = n & 7;
#pragma unroll
        for (int u = 0; u < 4; u++) {
            int id = tid + u * 256;
            int r = id >> 4;
            int c4 = (id & 15) * 4;
            int wmr = r >> 5, lr = r & 31;
            float mw0 = mls[r], mw1 = mls[64 + r], mw2 = mls[128 + r],
                  mw3 = mls[192 + r];
            float ms = fmaxf(fmaxf(mw0, mw1), fmaxf(mw2, mw3));
            float e0 = exp2f(mw0 - ms), e1 = exp2f(mw1 - ms),
                  e2 = exp2f(mw2 - ms), e3 = exp2f(mw3 - ms);
            float lt = lls[r] * e0 + lls[64 + r] * e1 + lls[128 + r] * e2 +
                       lls[192 + r] * e3;
            float4 s0 = *(float4*)&Ored[((wmr * 4 + 0) * 32 + lr) * OS + c4];
            float4 s1 = *(float4*)&Ored[((wmr * 4 + 1) * 32 + lr) * OS + c4];
            float4 s2 = *(float4*)&Ored[((wmr * 4 + 2) * 32 + lr) * OS + c4];
            float4 s3 = *(float4*)&Ored[((wmr * 4 + 3) * 32 + lr) * OS + c4];
            float inv = 1.0f / lt;
            float x = (s0.x * e0 + s1.x * e1 + s2.x * e2 + s3.x * e3) * inv;
            float y = (s0.y * e0 + s1.y * e1 + s2.y * e2 + s3.y * e3) * inv;
            float z = (s0.z * e0 + s1.z * e1 + s2.z * e2 + s3.z * e3) * inv;
            float w = (s0.w * e0 + s1.w * e1 + s2.w * e2 + s3.w * e3) * inv;
            __half h0, l0, h1, l1, h2, l2, h3, l3;
            split_h(x, h0, l0);
            split_h(y, h1, l1);
            split_h(z, h2, l2);
            split_h(w, h3, l3);
            size_t base = ((size_t)b * 1024 + m0 + r) * 512 + kh * 64 + c4;
            st_h2(&Ch[base], h0, h1);
            st_h2(&Ch[base + 2], h2, h3);
            st_h2(&Cl[base], l0, l1);
            st_h2(&Cl[base + 2], l2, l3);
        }
    }
}

// ---------------- launcher ----------------------------------------------------
extern "C" void kernel_launch(void* const* d_in, const int* in_sizes, int n_in,
                              void* d_out, int out_size) {
    const float* query = (const float*)d_in[0];
    const float* key = (const float*)d_in[1];
    const float* value = (const float*)d_in[2];
    const float* pos = (const float*)d_in[3];
    const float* Wq = (const float*)d_in[4];
    const float* Wk = (const float*)d_in[5];
    const float* Wv = (const float*)d_in[6];
    const float* Wo = (const float*)d_in[7];
    float* out = (float*)d_out;

    __half *qg, *kg, *vth, *et;
    __half *xq, *xk, *xv, *wqt, *wkt, *wvt, *wot, *ch, *cl;
    cudaGetSymbolAddress((void**)&qg, g_Qh);
    cudaGetSymbolAddress((void**)&kg, g_Kh);
    cudaGetSymbolAddress((void**)&vth, g_Vth);
    cudaGetSymbolAddress((void**)&et, g_Et);
    cudaGetSymbolAddress((void**)&xq, g_Xq16);
    cudaGetSymbolAddress((void**)&xk, g_Xk16);
    cudaGetSymbolAddress((void**)&xv, g_Xv16);
    cudaGetSymbolAddress((void**)&wqt, g_WqT16);
    cudaGetSymbolAddress((void**)&wkt, g_WkT16);
    cudaGetSymbolAddress((void**)&wvt, g_WvT16);
    cudaGetSymbolAddress((void**)&wot, g_WoT16);
    cudaGetSymbolAddress((void**)&ch, g_Ch);
    cudaGetSymbolAddress((void**)&cl, g_Cl);

    // prep (2 launches)
    conv_x_all<<<20480, 256>>>(query, key, value, xq, xk, xv);
    conv_wE_all<<<dim3(16, 16, 5), 256>>>(Wq, Wk, Wv, Wo, pos, wqt, wkt, wvt,
                                          wot, et);

    // projections (single-pass fp16; V writes V^T directly)
    const int hsm = 2 * 2 * TSZ * 2;  // 40960 bytes
    cudaFuncSetAttribute(gemm_h16<0>, cudaFuncAttributeMaxDynamicSharedMemorySize,
                         hsm);
    cudaFuncSetAttribute(gemm_h16<1>, cudaFuncAttributeMaxDynamicSharedMemorySize,
                         hsm);
    gemm_h16<0><<<dim3(64, 4), 256, hsm>>>(xq, wqt, qg, 1024);
    gemm_h16<0><<<dim3(128, 4), 256, hsm>>>(xk, wkt, kg, 2048);
    gemm_h16<1><<<dim3(128, 4), 256, hsm>>>(xv, wvt, vth, 2048);

    // attention (launch #6 -> profiled by ncu -s 5 -c 1)
    const int smem_bytes =
        (64 * 72 + 192 * 72 + 128 * 72 + 64 * 200) * 2 +
        (64 * 132 + 256 + 256) * 4;  // 115200
    cudaFuncSetAttribute(attn_tc13, cudaFuncAttributeMaxDynamicSharedMemorySize,
                         smem_bytes);
    attn_tc13<<<dim3(16, 64), 256, smem_bytes>>>(qg, kg, vth, et, ch, cl);

    // output projection (2-pass fp16)
    const int osm = 2 * 3 * TSZ * 2;  // 61440 bytes
    cudaFuncSetAttribute(gemm_out2, cudaFuncAttributeMaxDynamicSharedMemorySize,
                         osm);
    gemm_out2<<<dim3(64, 4), 256, osm>>>(ch, cl, wot, out);
}